// round 17
// baseline (speedup 1.0000x reference)
#include <cuda_runtime.h>
#include <cuda_fp16.h>
#include <cstdint>

// ============================================================================
// Problem constants
// ============================================================================
#define BATCH   4
#define SEQ     4096
#define DMODEL  1024
#define DK      64
#define ROWS    (BATCH * SEQ)        // 16384

// Projected tensors. q folded with mask*0.125*log2(e) -> logits in base-2.
__device__ __align__(16) __half g_qh [ROWS * DK];
__device__ __align__(16) __half g_kh [ROWS * DK];
__device__ __align__(16) __half g_vh [ROWS * DK];

// Pre-converted weights (fp16), 3 projections flat
__device__ __align__(16) __half g_Whi[3 * DMODEL * DK];

// split-K attention scratch: partial O in f16 (error budgeted), L in f32
#define ZSPLIT 4
__device__ __align__(16) __half g_Oacc[ZSPLIT][ROWS * DK];
__device__ float g_Lacc[ZSPLIT][ROWS];

// ============================================================================
// small helpers
// ============================================================================
__device__ __forceinline__ uint32_t cvta_smem(const void* p) {
    return (uint32_t)__cvta_generic_to_shared(p);
}

#define LDSM_X4(r0, r1, r2, r3, addr) \
    asm volatile("ldmatrix.sync.aligned.m8n8.x4.shared.b16 {%0,%1,%2,%3}, [%4];" \
        : "=r"(r0), "=r"(r1), "=r"(r2), "=r"(r3) : "r"(addr))

#define LDSM_X4_T(r0, r1, r2, r3, addr) \
    asm volatile("ldmatrix.sync.aligned.m8n8.x4.trans.shared.b16 {%0,%1,%2,%3}, [%4];" \
        : "=r"(r0), "=r"(r1), "=r"(r2), "=r"(r3) : "r"(addr))

#define MMA16816(d, a, b0, b1) \
    asm volatile("mma.sync.aligned.m16n8k16.row.col.f32.f16.f16.f32 " \
        "{%0,%1,%2,%3}, {%4,%5,%6,%7}, {%8,%9}, {%0,%1,%2,%3};" \
        : "+f"((d)[0]), "+f"((d)[1]), "+f"((d)[2]), "+f"((d)[3]) \
        : "r"((a)[0]), "r"((a)[1]), "r"((a)[2]), "r"((a)[3]), "r"(b0), "r"(b1))

// f16-accumulate MMA
#define MMA16816_F16(d, a, b0, b1) \
    asm volatile("mma.sync.aligned.m16n8k16.row.col.f16.f16.f16.f16 " \
        "{%0,%1}, {%2,%3,%4,%5}, {%6,%7}, {%0,%1};" \
        : "+r"((d)[0]), "+r"((d)[1]) \
        : "r"((a)[0]), "r"((a)[1]), "r"((a)[2]), "r"((a)[3]), "r"(b0), "r"(b1))

#define CP_ASYNC16(dst, src) \
    asm volatile("cp.async.cg.shared.global [%0], [%1], 16;" \
        :: "r"(dst), "l"(src) : "memory")
#define CP_COMMIT()  asm volatile("cp.async.commit_group;" ::: "memory")
#define CP_WAIT0()   asm volatile("cp.async.wait_group 0;" ::: "memory")

#define EX2_F16X2(dst, src) \
    asm volatile("ex2.approx.f16x2 %0, %1;" : "=r"(dst) : "r"(src))

__device__ __forceinline__ uint32_t pack_h2(float a, float b) {
    __half2 h = __floats2half2_rn(a, b);
    return *reinterpret_cast<uint32_t*>(&h);
}

// smem swizzle: row-major fp16 tiles, row = 128B = 8 chunks of 16B.
__device__ __forceinline__ uint32_t sw_off(int row, int chunk) {
    return (uint32_t)(row * 128 + ((chunk ^ (row & 7)) << 4));
}

// ============================================================================
// Weight pre-conversion: fp32 -> fp16, once.
// ============================================================================
__global__ __launch_bounds__(256) void wconv_kernel(
    const float* __restrict__ Wq, const float* __restrict__ Wk,
    const float* __restrict__ Wv)
{
    int i = blockIdx.x * 256 + threadIdx.x;
    int which = blockIdx.y;
    const float* W = (which == 0) ? Wq : (which == 1) ? Wk : Wv;
    g_Whi[which * DMODEL * DK + i] = __float2half_rn(W[i]);
}

// ============================================================================
// Unified projection: plain fp16 GEMM for q, k, v.
//   X prefetched as CONVERTED fp16 regs (16 regs, not 32) -> fits 5 CTAs/SM.
// ============================================================================
#define PJ_TILE 8192
#define QK_SMEM (4 * PJ_TILE)             // Xhi2 + Whi2 = 32KB
#define QK_XHI(s) ((s) * PJ_TILE)
#define QK_WHI(s) (16384 + (s) * PJ_TILE)

__device__ __forceinline__ uint4 load_x_h2(const float* src) {
    float4 a = *reinterpret_cast<const float4*>(src);
    float4 b = *reinterpret_cast<const float4*>(src + 4);
    uint4 hv;
    hv.x = pack_h2(a.x, a.y);
    hv.y = pack_h2(a.z, a.w);
    hv.z = pack_h2(b.x, b.y);
    hv.w = pack_h2(b.z, b.w);
    return hv;
}

__global__ __launch_bounds__(128, 5) void proj_all_kernel(
    const float* __restrict__ Xq, const float* __restrict__ Xk,
    const float* __restrict__ Xv,
    const float* __restrict__ bq, const float* __restrict__ bk,
    const float* __restrict__ bv,
    const float* __restrict__ mask)
{
    extern __shared__ __align__(16) char psm[];
    const uint32_t sbase = cvta_smem(psm);

    const int tid   = threadIdx.x;
    const int lane  = tid & 31;
    const int w     = tid >> 5;
    const int which = blockIdx.y;         // 0=q, 1=k, 2=v
    const int row0  = blockIdx.x * 64;
    const int g     = lane >> 2;
    const int t     = lane & 3;
    const int qq    = lane >> 3;
    const int rr    = lane & 7;

    const float* X    = (which == 0) ? Xq : (which == 1) ? Xk : Xv;
    const float* bias = (which == 0) ? bq : (which == 1) ? bk : bv;
    const __half* Whi = g_Whi + which * DMODEL * DK;

    const int sr[4] = { (tid) >> 3, (tid + 128) >> 3, (tid + 256) >> 3, (tid + 384) >> 3 };
    const int sc    = tid & 7;

    float O[8][4];
#pragma unroll
    for (int j = 0; j < 8; j++)
#pragma unroll
        for (int i = 0; i < 4; i++) O[j][i] = 0.f;

    // prologue: X(0) converted regs + W(0) cp.async into stage 0
    uint4 xh[4];
#pragma unroll
    for (int i = 0; i < 4; i++)
        xh[i] = load_x_h2(X + (size_t)(row0 + sr[i]) * DMODEL + sc * 8);
#pragma unroll
    for (int i = 0; i < 4; i++)
        CP_ASYNC16(sbase + QK_WHI(0) + sw_off(sr[i], sc),
                   Whi + (size_t)sr[i] * DK + sc * 8);
    CP_COMMIT();

    for (int kc = 0; kc < DMODEL / 64; kc++) {
        const int s = kc & 1;
        const int k0 = kc * 64;

        // store X(kc) fp16 regs -> swizzled smem
#pragma unroll
        for (int i = 0; i < 4; i++)
            *reinterpret_cast<uint4*>(psm + QK_XHI(s) + sw_off(sr[i], sc)) = xh[i];

        // prefetch X(kc+1) (load fp32 + convert immediately; short live range)
        if (kc + 1 < DMODEL / 64) {
#pragma unroll
            for (int i = 0; i < 4; i++)
                xh[i] = load_x_h2(X + (size_t)(row0 + sr[i]) * DMODEL
                                    + (k0 + 64) + sc * 8);
        }

        CP_WAIT0();        // W(kc) landed
        __syncthreads();   // STS visible; everyone done with stage s^1

        if (kc + 1 < DMODEL / 64) {
#pragma unroll
            for (int i = 0; i < 4; i++)
                CP_ASYNC16(sbase + QK_WHI(s ^ 1) + sw_off(sr[i], sc),
                           Whi + (size_t)(k0 + 64 + sr[i]) * DK + sc * 8);
            CP_COMMIT();
        }

        uint32_t aHi[4][4];
        {
            int arow = w * 16 + (qq & 1) * 8 + rr;
#pragma unroll
            for (int ss = 0; ss < 4; ss++) {
                uint32_t off = sw_off(arow, 2 * ss + (qq >> 1));
                LDSM_X4(aHi[ss][0], aHi[ss][1], aHi[ss][2], aHi[ss][3],
                        sbase + QK_XHI(s) + off);
            }
        }
        int brow_base = qq * 8 + rr;
#pragma unroll
        for (int j = 0; j < 8; j++) {
#pragma unroll
            for (int sp = 0; sp < 2; sp++) {
                int brow = 32 * sp + brow_base;
                uint32_t v0, v1, v2, v3;
                LDSM_X4_T(v0, v1, v2, v3, sbase + QK_WHI(s) + sw_off(brow, j));
                MMA16816(O[j], aHi[2 * sp],     v0, v1);
                MMA16816(O[j], aHi[2 * sp + 1], v2, v3);
            }
        }
    }

    const int row_a = row0 + w * 16 + g;
    const int row_b = row_a + 8;
    const float LOG2E_O8 = 0.125f * 1.4426950408889634f;
    const float sca = (which == 0) ? (mask[row_a] * LOG2E_O8) : 1.0f;
    const float scb = (which == 0) ? (mask[row_b] * LOG2E_O8) : 1.0f;
    __half* Y = (which == 0) ? g_qh : (which == 1) ? g_kh : g_vh;
#pragma unroll
    for (int j = 0; j < 8; j++) {
        int col = 8 * j + 2 * t;
        float b0 = bias[col], b1 = bias[col + 1];
        *reinterpret_cast<uint32_t*>(&Y[(size_t)row_a * DK + col]) =
            pack_h2((O[j][0] + b0) * sca, (O[j][1] + b1) * sca);
        *reinterpret_cast<uint32_t*>(&Y[(size_t)row_b * DK + col]) =
            pack_h2((O[j][2] + b0) * scb, (O[j][3] + b1) * scb);
    }
}

// ============================================================================
// FlashAttention (R16, unchanged): BR=64, f16-acc S, ex2.f16x2, ones-B L,
// f16 partial-O epilogue.
// ============================================================================
#define BR   64
#define BC   64
#define NKT_Z (SEQ / BC / ZSPLIT)      // 16 tiles per quarter

#define Q_BYTES     (BR * 128)
#define TILE_BYTES  (BC * 128)
#define STAGE_BYTES (2 * TILE_BYTES)               // K + V = 16KB
#define ATTN_SMEM   (Q_BYTES + 2 * STAGE_BYTES)    // 40960

__device__ __forceinline__ void prefetch_tile(char* stage, int b, int key0, int tid)
{
    const __half* srcs[2] = {g_kh, g_vh};
#pragma unroll
    for (int i = 0; i < 8; i++) {
        int idx = tid + i * 128;
        int arr = idx >> 9;
        int rem = idx & 511;
        int row = rem >> 3, c = rem & 7;
        const __half* g = srcs[arr] + ((size_t)b * SEQ + key0 + row) * DK + c * 8;
        uint32_t d = cvta_smem(stage + arr * TILE_BYTES) + sw_off(row, c);
        CP_ASYNC16(d, g);
    }
}

__global__ __launch_bounds__(128, 4) void attn_kernel()
{
    extern __shared__ char smem[];
    char* Qs = smem;
    char* St = smem + Q_BYTES;

    const int tid  = threadIdx.x;
    const int lane = tid & 31;
    const int w    = tid >> 5;
    const int b    = blockIdx.y;
    const int q0   = blockIdx.x * BR;
    const int z    = blockIdx.z;
    const int key_base = z * (SEQ / ZSPLIT);
    const int g    = lane >> 2;
    const int t    = lane & 3;
    const int qq   = lane >> 3;
    const int rr   = lane & 7;

    prefetch_tile(St, b, key_base, tid);
    CP_COMMIT();

    {
        const __half* qb = g_qh + ((size_t)b * SEQ + q0) * DK;
#pragma unroll
        for (int i = 0; i < 4; i++) {
            int idx = tid + i * 128;
            int row = idx >> 3, c = idx & 7;
            uint4 v = *reinterpret_cast<const uint4*>(qb + (size_t)row * DK + c * 8);
            *reinterpret_cast<uint4*>(Qs + sw_off(row, c)) = v;
        }
    }
    __syncthreads();

    uint32_t qA[4][4];
    {
        uint32_t qbase = cvta_smem(Qs);
        int row = w * 16 + (qq & 1) * 8 + rr;
#pragma unroll
        for (int s = 0; s < 4; s++) {
            uint32_t addr = qbase + sw_off(row, 2 * s + (qq >> 1));
            LDSM_X4(qA[s][0], qA[s][1], qA[s][2], qA[s][3], addr);
        }
    }

    float O[8][4];
#pragma unroll
    for (int j = 0; j < 8; j++)
#pragma unroll
        for (int i = 0; i < 4; i++) O[j][i] = 0.f;
    float OL[4] = {0.f, 0.f, 0.f, 0.f};
    const uint32_t ONE2 = 0x3C003C00u;

    for (int kt = 0; kt < NKT_Z; kt++) {
        const int s = kt & 1;
        char* stage = St + s * STAGE_BYTES;

        CP_WAIT0();
        __syncthreads();

        if (kt + 1 < NKT_Z) {
            prefetch_tile(St + (s ^ 1) * STAGE_BYTES, b,
                          key_base + (kt + 1) * BC, tid);
            CP_COMMIT();
        }

        const uint32_t kb  = cvta_smem(stage);
        const uint32_t vhb = kb + TILE_BYTES;

        uint32_t aP[4][4];
#pragma unroll
        for (int j = 0; j < 8; j++) {
            uint32_t dP[2] = {0u, 0u};
#pragma unroll
            for (int sp = 0; sp < 2; sp++) {
                int row = j * 8 + rr;
                uint32_t addr = kb + sw_off(row, 4 * sp + qq);
                uint32_t k0, k1, k2, k3;
                LDSM_X4(k0, k1, k2, k3, addr);
                MMA16816_F16(dP, qA[2 * sp],     k0, k1);
                MMA16816_F16(dP, qA[2 * sp + 1], k2, k3);
            }
            int sp2 = j >> 1, o = (j & 1) * 2;
            EX2_F16X2(aP[sp2][o],     dP[0]);
            EX2_F16X2(aP[sp2][o + 1], dP[1]);
        }

        MMA16816(OL, aP[0], ONE2, ONE2);
        MMA16816(OL, aP[1], ONE2, ONE2);
        MMA16816(OL, aP[2], ONE2, ONE2);
        MMA16816(OL, aP[3], ONE2, ONE2);

#pragma unroll
        for (int j = 0; j < 8; j++) {
#pragma unroll
            for (int sp = 0; sp < 2; sp++) {
                int row = 32 * sp + qq * 8 + rr;
                uint32_t v0, v1, v2, v3;
                LDSM_X4_T(v0, v1, v2, v3, vhb + sw_off(row, j));
                MMA16816(O[j], aP[2 * sp],     v0, v1);
                MMA16816(O[j], aP[2 * sp + 1], v2, v3);
            }
        }
    }

    // ---- epilogue: f16 partial O, f32 L ----
    const size_t row_a = (size_t)b * SEQ + q0 + w * 16 + g;
    const size_t row_b = row_a + 8;
    __half* Oz = g_Oacc[z];
    if (t == 0) {
        g_Lacc[z][row_a] = OL[0];
        g_Lacc[z][row_b] = OL[2];
    }
#pragma unroll
    for (int j = 0; j < 8; j++) {
        int col = 8 * j + 2 * t;
        *reinterpret_cast<uint32_t*>(&Oz[row_a * DK + col]) =
            pack_h2(O[j][0], O[j][1]);
        *reinterpret_cast<uint32_t*>(&Oz[row_b * DK + col]) =
            pack_h2(O[j][2], O[j][3]);
    }
}

// ============================================================================
// Normalize: out = sum_z O_z / sum_z L_z.  4 outputs/thread, 1024 blocks
// (R16 profile showed latency/occupancy bound; more threads, same MLP).
// ============================================================================
__global__ __launch_bounds__(256) void normalize_kernel(float* __restrict__ out)
{
    int idx = blockIdx.x * 256 + threadIdx.x;    // unit = 4 elements
    int row = idx >> 4;
    float Lsum = g_Lacc[0][row] + g_Lacc[1][row]
               + g_Lacc[2][row] + g_Lacc[3][row];
    float inv = 1.0f / Lsum;

    uint2 hz[ZSPLIT];
#pragma unroll
    for (int z = 0; z < ZSPLIT; z++)
        hz[z] = *reinterpret_cast<const uint2*>(&g_Oacc[z][(size_t)idx * 4]);

    float acc[4] = {0.f, 0.f, 0.f, 0.f};
#pragma unroll
    for (int z = 0; z < ZSPLIT; z++) {
        __half2 h0 = *reinterpret_cast<const __half2*>(&hz[z].x);
        __half2 h1 = *reinterpret_cast<const __half2*>(&hz[z].y);
        float2 f0 = __half22float2(h0);
        float2 f1 = __half22float2(h1);
        acc[0] += f0.x; acc[1] += f0.y;
        acc[2] += f1.x; acc[3] += f1.y;
    }

    float4 r = make_float4(acc[0] * inv, acc[1] * inv, acc[2] * inv, acc[3] * inv);
    *reinterpret_cast<float4*>(out + (size_t)idx * 4) = r;
}

// ============================================================================
extern "C" void kernel_launch(void* const* d_in, const int* in_sizes, int n_in,
                              void* d_out, int out_size)
{
    const float* q  = (const float*)d_in[0];
    const float* k  = (const float*)d_in[1];
    const float* v  = (const float*)d_in[2];
    const float* m  = (const float*)d_in[3];
    const float* Wq = (const float*)d_in[4];
    const float* bq = (const float*)d_in[5];
    const float* Wk = (const float*)d_in[6];
    const float* bk = (const float*)d_in[7];
    const float* Wv = (const float*)d_in[8];
    const float* bv = (const float*)d_in[9];
    float* out = (float*)d_out;

    cudaFuncSetAttribute(proj_all_kernel,
                         cudaFuncAttributeMaxDynamicSharedMemorySize, QK_SMEM);
    cudaFuncSetAttribute(attn_kernel,
                         cudaFuncAttributeMaxDynamicSharedMemorySize, ATTN_SMEM);

    dim3 wgrid(DMODEL * DK / 256, 3);
    wconv_kernel<<<wgrid, 256>>>(Wq, Wk, Wv);

    dim3 pgrid(ROWS / 64, 3);
    proj_all_kernel<<<pgrid, 128, QK_SMEM>>>(q, k, v, bq, bk, bv, m);

    dim3 grid(SEQ / BR, BATCH, ZSPLIT);
    attn_kernel<<<grid, 128, ATTN_SMEM>>>();

    normalize_kernel<<<ROWS * DK / 4 / 256, 256>>>(out);
}